// round 16
// baseline (speedup 1.0000x reference)
#include <cuda_runtime.h>
#include <cuda_bf16.h>
#include <cstdint>

#define MROWS   512   // rows of weight / output dim
#define KDIM    20    // motion dim
#define OUT_DIM 512
#define TILE_M  128   // batch rows per tile
#define KPAD    64    // split-K layout: A=[hi20|lo20|hi20|0], B=[hi20|hi20|lo20|0]
#define GTHREADS 256  // 8 warps, each owns 64 output cols
#define SROW_W  36    // A smem row stride in words -> conflict-free LDSM phases
#define GRID_P  296   // persistent: 2 CTAs/SM

#define AW       (TILE_M * SROW_W)     // 4608 words per A buffer
#define SLABROW  72                     // slab row stride (words): <=2-way STS banks
#define SLAB_W   (16 * SLABROW)         // 1152 words per slab
// dyn smem: [A0 | A1 | 8 warps x 2 slabs]
#define SMEM_WORDS (2 * AW + 8 * 2 * SLAB_W)
#define SMEM_BYTES (SMEM_WORDS * 4)     // 110592 B

// B' table (bf16): g_Qbf[n*64 + k]; k 0-19 = Qhi, 20-39 = Qhi, 40-59 = Qlo, 60-63 = 0
__device__ __align__(16) __nv_bfloat16 g_Qbf[OUT_DIM * KPAD];

// ---------------------------------------------------------------------------
// helpers
// ---------------------------------------------------------------------------
__device__ __forceinline__ uint32_t bf2pack(float a, float b) {
    __nv_bfloat162 t = __floats2bfloat162_rn(a, b);
    return *reinterpret_cast<uint32_t*>(&t);
}

__device__ __forceinline__ float blockReduceSum(float x, float* red) {
    int lane = threadIdx.x & 31;
    int wid  = threadIdx.x >> 5;
    #pragma unroll
    for (int off = 16; off; off >>= 1) x += __shfl_xor_sync(0xffffffffu, x, off);
    if (lane == 0) red[wid] = x;
    __syncthreads();
    float s = (lane < 16) ? red[lane] : 0.f;
    #pragma unroll
    for (int off = 8; off; off >>= 1) s += __shfl_xor_sync(0xffffffffu, s, off);
    s = __shfl_sync(0xffffffffu, s, 0);
    __syncthreads();
    return s;
}

__device__ __forceinline__ void mma16816(float* d,
                                         uint32_t a0, uint32_t a1, uint32_t a2, uint32_t a3,
                                         uint32_t b0, uint32_t b1) {
    asm("mma.sync.aligned.m16n8k16.row.col.f32.bf16.bf16.f32 "
        "{%0,%1,%2,%3}, {%4,%5,%6,%7}, {%8,%9}, {%0,%1,%2,%3};"
        : "+f"(d[0]), "+f"(d[1]), "+f"(d[2]), "+f"(d[3])
        : "r"(a0), "r"(a1), "r"(a2), "r"(a3), "r"(b0), "r"(b1));
}

__device__ __forceinline__ void ldsm_x4(uint32_t* r, uint32_t addr) {
    asm volatile("ldmatrix.sync.aligned.m8n8.x4.shared.b16 {%0,%1,%2,%3}, [%4];"
                 : "=r"(r[0]), "=r"(r[1]), "=r"(r[2]), "=r"(r[3]) : "r"(addr));
}

// bulk-async store machinery (base sm_90 PTX; NOT 'a'-gated)
__device__ __forceinline__ void bulk_store_256(float* gdst, uint32_t ssrc) {
    asm volatile("cp.async.bulk.global.shared::cta.bulk_group [%0], [%1], 256;"
                 :: "l"(gdst), "r"(ssrc) : "memory");
}
__device__ __forceinline__ void bulk_commit() {
    asm volatile("cp.async.bulk.commit_group;" ::: "memory");
}
template <int N>
__device__ __forceinline__ void bulk_wait_read() {
    asm volatile("cp.async.bulk.wait_group.read %0;" :: "n"(N) : "memory");
}
template <int N>
__device__ __forceinline__ void bulk_wait() {
    asm volatile("cp.async.bulk.wait_group %0;" :: "n"(N) : "memory");
}
__device__ __forceinline__ void fence_proxy_async_s() {
    asm volatile("fence.proxy.async.shared::cta;" ::: "memory");
}

// ---------------------------------------------------------------------------
// QR of W + 1e-8 (W: [512,20]) with LAPACK geqr2 signs, WITHOUT org2r:
//   geqr2 -> R; Rinv by back-substitution; Q = (W+1e-8) * Rinv.
// Emits bf16 hi/lo split table g_Qbf (B layout: [qh|qh|ql|0]).
// ---------------------------------------------------------------------------
__global__ void qr_kernel(const float* __restrict__ W) {
    __shared__ float sA[KDIM][MROWS];    // column-major: sA[c][t] = A[t][c]
    __shared__ float sV[MROWS];
    __shared__ float sRinv[KDIM][KDIM + 1];
    __shared__ float sRed[16];

    const int t    = threadIdx.x;
    const int lane = t & 31;
    const int wid  = t >> 5;

    float wrow[KDIM];                    // this thread's row of W + 1e-8
    #pragma unroll
    for (int c = 0; c < KDIM; ++c) {
        wrow[c] = W[t * KDIM + c] + 1e-8f;
        sA[c][t] = wrow[c];
    }
    __syncthreads();

    // ---- geqr2 ----
    for (int j = 0; j < KDIM; ++j) {
        float a  = sA[j][t];
        float sq = (t > j) ? a * a : 0.f;
        float xnorm2 = blockReduceSum(sq, sRed);
        float alpha  = sA[j][j];
        float beta   = -copysignf(sqrtf(alpha * alpha + xnorm2), alpha);  // LAPACK sign
        float tau    = (beta - alpha) / beta;
        float inv    = 1.f / (alpha - beta);
        float v      = (t == j) ? 1.f : ((t > j) ? a * inv : 0.f);
        sV[t] = v;
        if (t == j) sA[j][j] = beta;     // R diagonal
        __syncthreads();

        for (int c = j + 1 + wid; c < KDIM; c += 16) {
            float w = 0.f;
            #pragma unroll
            for (int i = lane; i < MROWS; i += 32) w += sV[i] * sA[c][i];
            #pragma unroll
            for (int off = 16; off; off >>= 1) w += __shfl_xor_sync(0xffffffffu, w, off);
            float tw = tau * w;
            #pragma unroll
            for (int i = lane; i < MROWS; i += 32) sA[c][i] -= tw * sV[i];
        }
        __syncthreads();
    }

    // ---- Rinv: thread c solves R x = e_c ----
    if (t < KDIM) {
        const int c = t;
        float x[KDIM];
        #pragma unroll
        for (int i = 0; i < KDIM; ++i) x[i] = 0.f;
        x[c] = 1.f / sA[c][c];
        for (int i = c - 1; i >= 0; --i) {
            float s = 0.f;
            for (int k = i + 1; k <= c; ++k) s += sA[k][i] * x[k];
            x[i] = -s / sA[i][i];
        }
        #pragma unroll
        for (int k = 0; k < KDIM; ++k) sRinv[k][c] = x[k];
    }
    __syncthreads();

    // ---- Q row t = wrow * Rinv; bf16 hi/lo split -> g_Qbf ----
    #pragma unroll
    for (int c = 0; c < KDIM; ++c) {
        float q = 0.f;
        for (int k = 0; k <= c; ++k) q += wrow[k] * sRinv[k][c];
        __nv_bfloat16 h = __float2bfloat16_rn(q);
        float lo = q - __bfloat162float(h);
        g_Qbf[t * KPAD + c]            = h;
        g_Qbf[t * KPAD + KDIM + c]     = h;
        g_Qbf[t * KPAD + 2 * KDIM + c] = __float2bfloat16_rn(lo);
    }
    #pragma unroll
    for (int k = 3 * KDIM; k < KPAD; ++k)
        g_Qbf[t * KPAD + k] = __float2bfloat16_rn(0.f);
}

// ---------------------------------------------------------------------------
// Persistent HMMA GEMM (R13 core) + bulk-async (TMA-path) stores.
// Per warp-subtile: stage 16x64 result into a warp-private smem slab (identity
// column layout, 72-word row stride -> ~2-way STS banks), fence.proxy.async,
// lanes 0-15 each issue ONE 256B cp.async.bulk per row. Two slabs per warp,
// wait_group.read<1> before reuse -> stores pipeline under next subtile's MMA
// and leave the SM via the TMA engine (no LSU store-buffer pressure).
// ---------------------------------------------------------------------------
__global__ void __launch_bounds__(GTHREADS, 2)
gemm_hmma_kernel(const float* __restrict__ input, float* __restrict__ out,
                 int batch, int ntiles) {
    extern __shared__ uint32_t dynsmem[];
    uint32_t* sW0  = dynsmem;
    uint32_t* sW1  = dynsmem + AW;
    uint32_t* sEpi = dynsmem + 2 * AW;

    const int tid  = threadIdx.x;
    const int wid  = tid >> 5;
    const int lane = tid & 31;
    const int g    = lane >> 2;        // fragment row group 0..7
    const int cq   = lane & 3;         // quad col: k pair base = 2*cq

    // ---- B fragments (once per block): B[j][t] = (B'[2cq+8t, n], B'[+1, n]) ----
    uint32_t Bf[8][8];
    {
        const uint32_t* qw = reinterpret_cast<const uint32_t*>(g_Qbf);
        const int nb = wid * 64 + g;
        #pragma unroll
        for (int j = 0; j < 8; ++j) {
            const uint32_t* qrow = qw + (nb + 8 * j) * (KPAD / 2) + cq;
            #pragma unroll
            for (int t = 0; t < 8; ++t)
                Bf[j][t] = qrow[4 * t];
        }
    }

    // ---- conversion: tile tt -> buffer buf ----
    auto convert_tile = [&](long long tt, int buf) {
        const int r = tid >> 1;                 // row 0..127
        const int h = tid & 1;                  // half: k0 = 10h
        const long long grow = tt * TILE_M + r;
        float2 v[5];
        if (grow < batch) {
            const float2* src = reinterpret_cast<const float2*>(input + grow * KDIM + 10 * h);
            #pragma unroll
            for (int p = 0; p < 5; ++p) v[p] = src[p];
        } else {
            #pragma unroll
            for (int p = 0; p < 5; ++p) v[p] = make_float2(0.f, 0.f);
        }
        uint32_t* row = (buf ? sW1 : sW0) + r * SROW_W;
        #pragma unroll
        for (int p = 0; p < 5; ++p) {
            const int k = 10 * h + 2 * p;
            float x0 = v[p].x, x1 = v[p].y;
            __nv_bfloat16 h0 = __float2bfloat16_rn(x0);
            __nv_bfloat16 h1 = __float2bfloat16_rn(x1);
            uint32_t hp = bf2pack(x0, x1);
            uint32_t lp = bf2pack(x0 - __bfloat162float(h0), x1 - __bfloat162float(h1));
            row[k / 2]      = hp;   // hi block
            row[10 + k / 2] = lp;   // lo block
            row[20 + k / 2] = hp;   // hi dup
        }
        if (h) { row[30] = 0u; row[31] = 0u; }   // k 60..63 = 0
    };

    // ldmatrix lane address base: row = (lane&15), k-half = (lane&16)?words 4..7
    const uint32_t smem0 = (uint32_t)__cvta_generic_to_shared(sW0);
    const uint32_t smem1 = (uint32_t)__cvta_generic_to_shared(sW1);
    const uint32_t lane_off = (((lane & 15) * SROW_W + ((lane & 16) ? 4 : 0)) * 4);

    // per-warp slabs (identity column layout; row stride 72 words)
    uint32_t* slab0 = sEpi + wid * (2 * SLAB_W);
    uint32_t* slab1 = slab0 + SLAB_W;
    const uint32_t slab0_s = (uint32_t)__cvta_generic_to_shared(slab0);
    const uint32_t slab1_s = (uint32_t)__cvta_generic_to_shared(slab1);

    const long long stride = gridDim.x;
    const long long t0 = blockIdx.x;

    if (t0 < ntiles) convert_tile(t0, 0);
    __syncthreads();

    int buf = 0;
    for (long long t = t0; t < ntiles; t += stride) {
        // prefetch-convert next tile into the other buffer (overlaps MMAs below)
        const long long tn = t + stride;
        if (tn < ntiles) convert_tile(tn, buf ^ 1);

        const long long tb = t * TILE_M;
        const uint32_t sbase = (buf ? smem1 : smem0) + lane_off;

        #pragma unroll 1
        for (int ms = 0; ms < 8; ++ms) {
            const uint32_t mbase = sbase + (uint32_t)(16 * ms * SROW_W * 4);
            uint32_t* cur        = (ms & 1) ? slab1 : slab0;
            const uint32_t cur_s = (ms & 1) ? slab1_s : slab0_s;

            float acc[8][4];
            #pragma unroll
            for (int j = 0; j < 8; ++j)
                acc[j][0] = acc[j][1] = acc[j][2] = acc[j][3] = 0.f;

            #pragma unroll
            for (int s = 0; s < 4; ++s) {
                uint32_t a[4];
                ldsm_x4(a, mbase + 32u * s);   // 8 words per k16 chunk
                #pragma unroll
                for (int j = 0; j < 8; ++j)
                    mma16816(acc[j], a[0], a[1], a[2], a[3],
                             Bf[j][2 * s], Bf[j][2 * s + 1]);
            }

            // slab reuse: the copy issued from this slab 2 subtiles ago must
            // have finished READING it (writes may still be in flight).
            if (lane < 16) bulk_wait_read<1>();
            __syncwarp();

            // stage (identity layout): rows g, g+8; cols 8j + 2cq
            #pragma unroll
            for (int rr = 0; rr < 2; ++rr) {
                uint32_t* base = cur + (g + 8 * rr) * SLABROW;
                #pragma unroll
                for (int j = 0; j < 8; ++j)
                    *reinterpret_cast<float2*>(base + 8 * j + 2 * cq) =
                        make_float2(acc[j][2 * rr], acc[j][2 * rr + 1]);
            }
            __syncwarp();

            // lanes 0-15: one 256B bulk store per row
            const long long rowbase = tb + 16 * ms;
            if (lane < 16) {
                const long long grow = rowbase + lane;
                if (grow < batch) {
                    fence_proxy_async_s();
                    bulk_store_256(out + grow * OUT_DIM + wid * 64,
                                   cur_s + lane * (SLABROW * 4));
                }
                bulk_commit();   // unconditional: uniform group counting
            }
        }

        __syncthreads();   // A next buffer fully written; old A buffer free
        buf ^= 1;
    }

    // drain all outstanding bulk stores before exit
    if (lane < 16) bulk_wait<0>();
}

// ---------------------------------------------------------------------------
extern "C" void kernel_launch(void* const* d_in, const int* in_sizes, int n_in,
                              void* d_out, int out_size) {
    const float* input  = (const float*)d_in[0];
    const float* weight = (const float*)d_in[1];
    int s0 = in_sizes[0], s1 = in_sizes[1];
    if (s0 < s1) {
        const float* tmp = input; input = weight; weight = tmp;
        int ts = s0; s0 = s1; s1 = ts;
    }
    const int batch  = s0 / KDIM;
    const int ntiles = (batch + TILE_M - 1) / TILE_M;

    cudaFuncSetAttribute(gemm_hmma_kernel,
                         cudaFuncAttributeMaxDynamicSharedMemorySize, SMEM_BYTES);

    qr_kernel<<<1, MROWS>>>(weight);
    gemm_hmma_kernel<<<GRID_P, GTHREADS, SMEM_BYTES>>>(input, (float*)d_out, batch, ntiles);
}

// round 17
// speedup vs baseline: 1.0490x; 1.0490x over previous
#include <cuda_runtime.h>
#include <cuda_bf16.h>
#include <cstdint>

#define MROWS   512   // rows of weight / output dim
#define KDIM    20    // motion dim
#define OUT_DIM 512
#define TILE_M  128   // batch rows per tile
#define KPAD    64    // split-K layout: A=[hi20|lo20|hi20|0], B=[hi20|hi20|lo20|0]
#define GTHREADS 256  // 8 warps, each owns 64 output cols
#define SROW_W  36    // A smem row stride in words -> conflict-free LDSM phases
#define GRID_P  296   // persistent: 2 CTAs/SM (all co-resident -> spin is safe)

#define AW        (TILE_M * SROW_W)    // 4608 words per A buffer
#define QR_WORDS  (KDIM * MROWS + MROWS + KDIM * (KDIM + 1) + 8)   // 11180
#define GEMM_WORDS (2 * AW)                                         // 9216
#define DYN_WORDS (QR_WORDS > GEMM_WORDS ? QR_WORDS : GEMM_WORDS)
#define SMEM_BYTES (DYN_WORDS * 4)

// B' table (bf16): g_Qbf[n*64 + k]; k 0-19 = Qhi, 20-39 = Qhi, 40-59 = Qlo, 60-63 = 0
__device__ __align__(16) __nv_bfloat16 g_Qbf[OUT_DIM * KPAD];

// cross-block coordination (reset by the last block each launch/replay)
__device__ unsigned int g_tile = 0;   // dynamic tile counter
__device__ unsigned int g_flag = 0;   // Q-ready flag
__device__ unsigned int g_done = 0;   // finished-block counter

// ---------------------------------------------------------------------------
// helpers
// ---------------------------------------------------------------------------
__device__ __forceinline__ uint32_t bf2pack(float a, float b) {
    __nv_bfloat162 t = __floats2bfloat162_rn(a, b);
    return *reinterpret_cast<uint32_t*>(&t);
}

__device__ __forceinline__ void mma16816(float* d,
                                         uint32_t a0, uint32_t a1, uint32_t a2, uint32_t a3,
                                         uint32_t b0, uint32_t b1) {
    asm("mma.sync.aligned.m16n8k16.row.col.f32.bf16.bf16.f32 "
        "{%0,%1,%2,%3}, {%4,%5,%6,%7}, {%8,%9}, {%0,%1,%2,%3};"
        : "+f"(d[0]), "+f"(d[1]), "+f"(d[2]), "+f"(d[3])
        : "r"(a0), "r"(a1), "r"(a2), "r"(a3), "r"(b0), "r"(b1));
}

__device__ __forceinline__ void ldsm_x4(uint32_t* r, uint32_t addr) {
    asm volatile("ldmatrix.sync.aligned.m8n8.x4.shared.b16 {%0,%1,%2,%3}, [%4];"
                 : "=r"(r[0]), "=r"(r[1]), "=r"(r[2]), "=r"(r[3]) : "r"(addr));
}

__device__ __forceinline__ void stg_cs_v2(float* p, float x, float y) {
    asm volatile("st.global.cs.v2.f32 [%0], {%1, %2};" :: "l"(p), "f"(x), "f"(y) : "memory");
}

__device__ __forceinline__ uint32_t ld_acq(const unsigned int* p) {
    uint32_t v;
    asm volatile("ld.acquire.gpu.global.u32 %0, [%1];" : "=r"(v) : "l"(p) : "memory");
    return v;
}
__device__ __forceinline__ void st_rel(unsigned int* p, uint32_t v) {
    asm volatile("st.release.gpu.global.u32 [%0], %1;" :: "l"(p), "r"(v) : "memory");
}

// ---------------------------------------------------------------------------
// QR of W + 1e-8 (W: [512,20]) with LAPACK geqr2 signs, no org2r:
//   geqr2 -> R; Rinv by back-substitution; Q = (W+1e-8) * Rinv.
// 256 threads (2 rows each). Writes g_Qbf. Uses `pool` (>= QR_WORDS floats).
// ---------------------------------------------------------------------------
__device__ void qr_compute(float* pool, const float* __restrict__ W, int tid) {
    float (*sA)[MROWS] = reinterpret_cast<float (*)[MROWS]>(pool);  // [KDIM][512]
    float* sV    = pool + KDIM * MROWS;
    float* sRinv = sV + MROWS;                      // [KDIM][KDIM+1] flattened
    float* sRed  = sRinv + KDIM * (KDIM + 1);
    const int lane = tid & 31;
    const int w    = tid >> 5;

    #pragma unroll
    for (int c = 0; c < KDIM; ++c) {
        sA[c][tid]       = W[tid * KDIM + c] + 1e-8f;
        sA[c][tid + 256] = W[(tid + 256) * KDIM + c] + 1e-8f;
    }
    __syncthreads();

    for (int j = 0; j < KDIM; ++j) {
        const float alpha = sA[j][j];          // read BEFORE any write this iter
        const float a0 = sA[j][tid];
        const float a1 = sA[j][tid + 256];     // row >= 256 > j always
        float sq = ((tid > j) ? a0 * a0 : 0.f) + a1 * a1;
        #pragma unroll
        for (int off = 16; off; off >>= 1) sq += __shfl_xor_sync(0xffffffffu, sq, off);
        if (lane == 0) sRed[w] = sq;
        __syncthreads();
        float xn = (lane < 8) ? sRed[lane] : 0.f;
        #pragma unroll
        for (int off = 4; off; off >>= 1) xn += __shfl_xor_sync(0xffffffffu, xn, off);
        xn = __shfl_sync(0xffffffffu, xn, 0);
        __syncthreads();

        const float beta = -copysignf(sqrtf(alpha * alpha + xn), alpha);  // LAPACK sign
        const float tau  = (beta - alpha) / beta;
        const float inv  = 1.f / (alpha - beta);
        sV[tid]       = (tid == j) ? 1.f : ((tid > j) ? a0 * inv : 0.f);
        sV[tid + 256] = a1 * inv;
        if (tid == j) sA[j][j] = beta;         // R diagonal
        __syncthreads();

        for (int c = j + 1 + w; c < KDIM; c += 8) {
            float s = 0.f;
            #pragma unroll
            for (int i = lane; i < MROWS; i += 32) s += sV[i] * sA[c][i];
            #pragma unroll
            for (int off = 16; off; off >>= 1) s += __shfl_xor_sync(0xffffffffu, s, off);
            const float tw = tau * s;
            #pragma unroll
            for (int i = lane; i < MROWS; i += 32) sA[c][i] -= tw * sV[i];
        }
        __syncthreads();
    }

    // Rinv: thread c solves R x = e_c (R[r][c] = sA[c][r], r <= c)
    if (tid < KDIM) {
        const int c = tid;
        float x[KDIM];
        #pragma unroll
        for (int i = 0; i < KDIM; ++i) x[i] = 0.f;
        x[c] = 1.f / sA[c][c];
        for (int i = c - 1; i >= 0; --i) {
            float s = 0.f;
            for (int k = i + 1; k <= c; ++k) s += sA[k][i] * x[k];
            x[i] = -s / sA[i][i];
        }
        #pragma unroll
        for (int k = 0; k < KDIM; ++k) sRinv[k * (KDIM + 1) + c] = x[k];
    }
    __syncthreads();

    // Q rows tid, tid+256: q = wrow * Rinv; bf16 hi/lo split -> g_Qbf
    #pragma unroll
    for (int rr = 0; rr < 2; ++rr) {
        const int r = tid + 256 * rr;
        float wr[KDIM];
        #pragma unroll
        for (int k = 0; k < KDIM; ++k) wr[k] = W[r * KDIM + k] + 1e-8f;
        #pragma unroll
        for (int c = 0; c < KDIM; ++c) {
            float q = 0.f;
            for (int k = 0; k <= c; ++k) q += wr[k] * sRinv[k * (KDIM + 1) + c];
            __nv_bfloat16 h = __float2bfloat16_rn(q);
            float lo = q - __bfloat162float(h);
            g_Qbf[r * KPAD + c]            = h;
            g_Qbf[r * KPAD + KDIM + c]     = h;
            g_Qbf[r * KPAD + 2 * KDIM + c] = __float2bfloat16_rn(lo);
        }
        #pragma unroll
        for (int k = 3 * KDIM; k < KPAD; ++k)
            g_Qbf[r * KPAD + k] = __float2bfloat16_rn(0.f);
    }
}

// ---------------------------------------------------------------------------
// FUSED persistent kernel: block 0 computes QR while other blocks convert
// their first A tile; everyone then streams tiles from a global atomic
// counter (dynamic stealing absorbs block 0's QR cost and wave spread).
// GEMM core = R13 (best known): HMMA, register-resident Bf, ldmatrix A frags,
// double-buffered A smem, scattered st.global.cs.v2 stores.
// ---------------------------------------------------------------------------
__global__ void __launch_bounds__(GTHREADS, 2)
fused_kernel(const float* __restrict__ weight, const float* __restrict__ input,
             float* __restrict__ out, int batch, int ntiles) {
    extern __shared__ uint32_t dynsmem[];
    uint32_t* sW0 = dynsmem;
    uint32_t* sW1 = dynsmem + AW;
    __shared__ unsigned int sNext;

    const int tid  = threadIdx.x;
    const int wid  = tid >> 5;
    const int lane = tid & 31;
    const int g    = lane >> 2;        // fragment row group 0..7
    const int cq   = lane & 3;         // quad col: k pair base = 2*cq

    // ---- phase 0: QR on block 0 (others proceed straight to first convert) ----
    if (blockIdx.x == 0) {
        qr_compute(reinterpret_cast<float*>(dynsmem), weight, tid);
        __threadfence();
        __syncthreads();
        if (tid == 0) st_rel(&g_flag, 1u);
    }

    // ---- conversion: tile tt -> buffer buf ----
    auto convert_tile = [&](unsigned int tt, int buf) {
        const int r = tid >> 1;                 // row 0..127
        const int h = tid & 1;                  // half: k0 = 10h
        const long long grow = (long long)tt * TILE_M + r;
        float2 v[5];
        if (grow < batch) {
            const float2* src = reinterpret_cast<const float2*>(input + grow * KDIM + 10 * h);
            #pragma unroll
            for (int p = 0; p < 5; ++p) v[p] = src[p];
        } else {
            #pragma unroll
            for (int p = 0; p < 5; ++p) v[p] = make_float2(0.f, 0.f);
        }
        uint32_t* row = (buf ? sW1 : sW0) + r * SROW_W;
        #pragma unroll
        for (int p = 0; p < 5; ++p) {
            const int k = 10 * h + 2 * p;
            float x0 = v[p].x, x1 = v[p].y;
            __nv_bfloat16 h0 = __float2bfloat16_rn(x0);
            __nv_bfloat16 h1 = __float2bfloat16_rn(x1);
            uint32_t hp = bf2pack(x0, x1);
            uint32_t lp = bf2pack(x0 - __bfloat162float(h0), x1 - __bfloat162float(h1));
            row[k / 2]      = hp;   // hi block
            row[10 + k / 2] = lp;   // lo block
            row[20 + k / 2] = hp;   // hi dup
        }
        if (h) { row[30] = 0u; row[31] = 0u; }   // k 60..63 = 0
    };

    // ---- grab + convert first tile (overlaps block 0's QR on other blocks) ----
    if (tid == 0) sNext = atomicAdd(&g_tile, 1u);
    __syncthreads();
    unsigned int t_cur = sNext;
    if (t_cur < (unsigned int)ntiles) convert_tile(t_cur, 0);

    // ---- wait for Q ready ----
    if (tid == 0) {
        while (ld_acq(&g_flag) == 0u) __nanosleep(64);
    }
    __syncthreads();

    // ---- B fragments (once per block): B[j][t] = (B'[2cq+8t, n], B'[+1, n]) ----
    uint32_t Bf[8][8];
    {
        const uint32_t* qw = reinterpret_cast<const uint32_t*>(g_Qbf);
        const int nb = wid * 64 + g;
        #pragma unroll
        for (int j = 0; j < 8; ++j) {
            const uint32_t* qrow = qw + (nb + 8 * j) * (KPAD / 2) + cq;
            #pragma unroll
            for (int t = 0; t < 8; ++t)
                Bf[j][t] = qrow[4 * t];
        }
    }

    // ldmatrix lane address base
    const uint32_t smem0 = (uint32_t)__cvta_generic_to_shared(sW0);
    const uint32_t smem1 = (uint32_t)__cvta_generic_to_shared(sW1);
    const uint32_t lane_off = (((lane & 15) * SROW_W + ((lane & 16) ? 4 : 0)) * 4);
    const int colbase = wid * 64 + 2 * cq;

    if (tid == 0) sNext = atomicAdd(&g_tile, 1u);
    __syncthreads();                 // covers first convert + sNext
    unsigned int t_next = sNext;

    int buf = 0;
    while (t_cur < (unsigned int)ntiles) {
        if (t_next < (unsigned int)ntiles) convert_tile(t_next, buf ^ 1);

        const long long tb = (long long)t_cur * TILE_M;
        const uint32_t sbase = (buf ? smem1 : smem0) + lane_off;

        #pragma unroll 1
        for (int ms = 0; ms < 8; ++ms) {
            const uint32_t mbase = sbase + (uint32_t)(16 * ms * SROW_W * 4);

            float acc[8][4];
            #pragma unroll
            for (int j = 0; j < 8; ++j)
                acc[j][0] = acc[j][1] = acc[j][2] = acc[j][3] = 0.f;

            #pragma unroll
            for (int s = 0; s < 4; ++s) {
                uint32_t a[4];
                ldsm_x4(a, mbase + 32u * s);   // 8 words per k16 chunk
                #pragma unroll
                for (int j = 0; j < 8; ++j)
                    mma16816(acc[j], a[0], a[1], a[2], a[3],
                             Bf[j][2 * s], Bf[j][2 * s + 1]);
            }

            const long long grow0 = tb + 16 * ms + g;
            if (grow0 < batch) {
                float* p0 = out + grow0 * OUT_DIM + colbase;
                #pragma unroll
                for (int j = 0; j < 8; ++j)
                    stg_cs_v2(p0 + 8 * j, acc[j][0], acc[j][1]);
            }
            if (grow0 + 8 < batch) {
                float* p1 = out + (grow0 + 8) * OUT_DIM + colbase;
                #pragma unroll
                for (int j = 0; j < 8; ++j)
                    stg_cs_v2(p1 + 8 * j, acc[j][2], acc[j][3]);
            }
        }

        if (tid == 0) sNext = atomicAdd(&g_tile, 1u);
        __syncthreads();   // next buffer converted; old buffer free; sNext visible
        t_cur = t_next;
        t_next = sNext;
        buf ^= 1;
    }

    // ---- replay-safe reset: last block to finish clears the coordination state ----
    if (tid == 0) {
        __threadfence();
        unsigned int old = atomicAdd(&g_done, 1u);
        if (old == gridDim.x - 1) {
            atomicExch(&g_tile, 0u);
            atomicExch(&g_flag, 0u);
            atomicExch(&g_done, 0u);
            __threadfence();
        }
    }
}

// ---------------------------------------------------------------------------
extern "C" void kernel_launch(void* const* d_in, const int* in_sizes, int n_in,
                              void* d_out, int out_size) {
    const float* input  = (const float*)d_in[0];
    const float* weight = (const float*)d_in[1];
    int s0 = in_sizes[0], s1 = in_sizes[1];
    if (s0 < s1) {
        const float* tmp = input; input = weight; weight = tmp;
        int ts = s0; s0 = s1; s1 = ts;
    }
    const int batch  = s0 / KDIM;
    const int ntiles = (batch + TILE_M - 1) / TILE_M;

    cudaFuncSetAttribute(fused_kernel,
                         cudaFuncAttributeMaxDynamicSharedMemorySize, SMEM_BYTES);

    fused_kernel<<<GRID_P, GTHREADS, SMEM_BYTES>>>(weight, input, (float*)d_out,
                                                   batch, ntiles);
}